// round 15
// baseline (speedup 1.0000x reference)
#include <cuda_runtime.h>
#include <cuda_fp16.h>

#define SEQL 20
#define EMB  20
#define NMAX 671744
#define EMAX 4000000
#define NBATCH 8192
#define HID  300
#define NC   22
#define LAT  1640   // 82*20

// ---------------- scratch (static device globals; no runtime alloc) -------
__device__ int   g_deg[NMAX];
__device__ float g_dinv[NMAX];
__device__ __align__(16) uint4 g_hsh[(size_t)NMAX * 3];   // fp16 messages, 48B/row (40B valid)
__device__ float g_agg[(size_t)NMAX * EMB];   // fp32 aggregation buffer
__device__ int   g_src[EMAX];
__device__ int   g_dst[EMAX];
__device__ float g_fc1[(size_t)NBATCH * HID];
__device__ int   g_is64;

// ---------------- helpers -------------------------------------------------
__device__ __forceinline__ void red_add_v4(float* p, float4 v) {
    asm volatile("red.global.add.v4.f32 [%0], {%1,%2,%3,%4};"
                 :: "l"(p), "f"(v.x), "f"(v.y), "f"(v.z), "f"(v.w) : "memory");
}
__device__ __forceinline__ unsigned cvt_tf32(float f) {
    unsigned u;
    asm("cvt.rna.tf32.f32 %0, %1;" : "=r"(u) : "f"(f));
    return u;
}
__device__ __forceinline__ void mma_tf32(float& d0, float& d1, float& d2, float& d3,
                                         unsigned a0, unsigned a1, unsigned a2, unsigned a3,
                                         unsigned b0, unsigned b1) {
    asm("mma.sync.aligned.m16n8k8.row.col.f32.tf32.tf32.f32 "
        "{%0,%1,%2,%3}, {%4,%5,%6,%7}, {%8,%9}, {%0,%1,%2,%3};"
        : "+f"(d0), "+f"(d1), "+f"(d2), "+f"(d3)
        : "r"(a0), "r"(a1), "r"(a2), "r"(a3), "r"(b0), "r"(b1));
}
// write one node row: o[0..19]*dinv -> fp16x2 packed 48B (+agg fp32 seed)
__device__ __forceinline__ void store_row(int i, const float* o, float dinv) {
    __half2 hh[12];
#pragma unroll
    for (int j = 0; j < 10; j++)
        hh[j] = __floats2half2_rn(o[2*j] * dinv, o[2*j+1] * dinv);
    hh[10] = hh[11] = __float2half2_rn(0.f);
    uint4* hp = &g_hsh[(size_t)i * 3];
    const uint4* src = (const uint4*)hh;
    hp[0] = src[0]; hp[1] = src[1]; hp[2] = src[2];
    float4* ap = (float4*)(g_agg + (size_t)i * EMB);
#pragma unroll
    for (int q = 0; q < EMB / 4; q++)
        ap[q] = make_float4(o[4*q]*dinv, o[4*q+1]*dinv, o[4*q+2]*dinv, o[4*q+3]*dinv);
}

// ---- launch 1: dtype detect + deg := 1 (self loop) -----------------------
__global__ void k_init(const int* __restrict__ ei32, int n) {
    int i = blockIdx.x * blockDim.x + threadIdx.x;
    if (i < n) g_deg[i] = 1;           // self loop
    if (blockIdx.x == 0 && threadIdx.x == 0) {
        int all0 = 1;
        for (int q = 1; q < 257; q += 2)
            if (ei32[q] != 0) { all0 = 0; break; }
        g_is64 = all0;   // int64 little-endian: high words of small values are 0
    }
}

// ---- launch 2: stage edges to int32 + degree count -----------------------
__global__ void k_edges_prep(const void* __restrict__ eiv, int E) {
    int e = blockIdx.x * blockDim.x + threadIdx.x;
    if (e >= E) return;
    int s, d;
    if (g_is64) {
        const long long* p = (const long long*)eiv;
        s = (int)p[e];
        d = (int)p[(size_t)E + e];
    } else {
        const int* p = (const int*)eiv;
        s = p[e];
        d = p[E + e];
    }
    g_src[e] = s;
    g_dst[e] = d;
    atomicAdd(&g_deg[d], 1);
}

// ---- launch 3: msg(fp16) = (x @ W1)*dinv ; agg(fp32) = same (self seed) --
__global__ __launch_bounds__(256) void k_layer1(const float* __restrict__ x,
                                                const float* __restrict__ W,
                                                int n) {
    __shared__ __align__(16) float sW[SEQL * EMB];
    for (int t = threadIdx.x; t < SEQL * EMB; t += 256) sW[t] = W[t];
    __syncthreads();
    int i = blockIdx.x * 256 + threadIdx.x;
    if (i >= n) return;
    float dinv = rsqrtf((float)g_deg[i]);
    g_dinv[i] = dinv;
    float xi[SEQL];
    const float4* xp = (const float4*)(x + (size_t)i * SEQL);
#pragma unroll
    for (int q = 0; q < SEQL / 4; q++) {
        float4 v = __ldg(xp + q);
        xi[4*q] = v.x; xi[4*q+1] = v.y; xi[4*q+2] = v.z; xi[4*q+3] = v.w;
    }
    float o[EMB];
#pragma unroll
    for (int j = 0; j < EMB; j++) o[j] = 0.f;
#pragma unroll
    for (int k = 0; k < SEQL; k++) {
        float xk = xi[k];
#pragma unroll
        for (int q = 0; q < EMB / 4; q++) {
            float4 w = *(const float4*)&sW[k * EMB + 4 * q];
            o[4*q]   = fmaf(xk, w.x, o[4*q]);
            o[4*q+1] = fmaf(xk, w.y, o[4*q+1]);
            o[4*q+2] = fmaf(xk, w.z, o[4*q+2]);
            o[4*q+3] = fmaf(xk, w.w, o[4*q+3]);
        }
    }
    store_row(i, o, dinv);
}

// ---- launch 4 (ncu slot): agg[dst] += msg[src]  (48B fp16 read, fp32 RED)
__global__ __launch_bounds__(256) void k_scatter(int E) {
    int e = blockIdx.x * blockDim.x + threadIdx.x;
    if (e >= E) return;
    int s = g_src[e], d = g_dst[e];
    const uint4* hp = &g_hsh[(size_t)s * 3];
    uint4 u0 = __ldg(hp), u1 = __ldg(hp + 1), u2 = __ldg(hp + 2);
    __half2 hh[12];
    uint4* hv = (uint4*)hh;
    hv[0] = u0; hv[1] = u1; hv[2] = u2;
    float f[EMB];
#pragma unroll
    for (int j = 0; j < 10; j++) {
        float2 t = __half22float2(hh[j]);
        f[2*j] = t.x; f[2*j+1] = t.y;
    }
    float* ap = g_agg + (size_t)d * EMB;
#pragma unroll
    for (int q = 0; q < EMB / 4; q++)
        red_add_v4(ap + 4 * q, make_float4(f[4*q], f[4*q+1], f[4*q+2], f[4*q+3]));
}

// ---- t = relu(agg*dinv + b1);  o = (t @ W2)*dinv -> msg fp16 + agg seed --
__global__ __launch_bounds__(256) void k_layer2(const float* __restrict__ b1,
                                                const float* __restrict__ W,
                                                int n) {
    __shared__ __align__(16) float sW[EMB * EMB];
    __shared__ float sb[EMB];
    for (int t = threadIdx.x; t < EMB * EMB; t += 256) sW[t] = W[t];
    if (threadIdx.x < EMB) sb[threadIdx.x] = b1[threadIdx.x];
    __syncthreads();
    int i = blockIdx.x * 256 + threadIdx.x;
    if (i >= n) return;
    float dinv = g_dinv[i];
    float ti[EMB];
    const float4* ap_in = (const float4*)(g_agg + (size_t)i * EMB);
#pragma unroll
    for (int q = 0; q < EMB / 4; q++) {
        float4 v = ap_in[q];
        ti[4*q]   = fmaxf(fmaf(v.x, dinv, sb[4*q]),   0.f);
        ti[4*q+1] = fmaxf(fmaf(v.y, dinv, sb[4*q+1]), 0.f);
        ti[4*q+2] = fmaxf(fmaf(v.z, dinv, sb[4*q+2]), 0.f);
        ti[4*q+3] = fmaxf(fmaf(v.w, dinv, sb[4*q+3]), 0.f);
    }
    float o[EMB];
#pragma unroll
    for (int j = 0; j < EMB; j++) o[j] = 0.f;
#pragma unroll
    for (int k = 0; k < EMB; k++) {
        float tk = ti[k];
#pragma unroll
        for (int q = 0; q < EMB / 4; q++) {
            float4 w = *(const float4*)&sW[k * EMB + 4 * q];
            o[4*q]   = fmaf(tk, w.x, o[4*q]);
            o[4*q+1] = fmaf(tk, w.y, o[4*q+1]);
            o[4*q+2] = fmaf(tk, w.z, o[4*q+2]);
            o[4*q+3] = fmaf(tk, w.w, o[4*q+3]);
        }
    }
    store_row(i, o, dinv);
}

// fc1 (tf32 tensor cores, fused final, double-buffered):
// A[r][c] = relu(agg[r*1640+c]*dinv + b2) computed in the A-tile load.
// BM=128 BN=64 BK=16; 8 warps (4x2), warp tile 32x32; mma.m16n8k8.
// Two smem buffers; tile i+1's LDGs issue before tile i's MMAs.
#define BM 128
#define BN 64
#define BK 16
#define NITER ((LAT + BK - 1) / BK)   // 103
__global__ __launch_bounds__(256) void k_fc1(const float* __restrict__ Wf,
                                             const float* __restrict__ bf,
                                             const float* __restrict__ b2) {
    __shared__ unsigned As[2][BK][136];   // [buf][k][m], tf32 bits
    __shared__ unsigned Bs[2][BK][72];    // [buf][k][n], tf32 bits
    __shared__ float sb2[EMB];
    const int tid  = threadIdx.x;
    const int lane = tid & 31;
    const int wid  = tid >> 5;         // 0..7
    const int warp_m = wid & 3;        // 0..3  (32 rows each)
    const int warp_n = wid >> 2;       // 0..1  (32 cols each)
    const int row0 = blockIdx.x * BM;
    const int col0 = blockIdx.y * BN;
    const int g  = lane >> 2;          // 0..7
    const int tg = lane & 3;           // 0..3

    const int arow = tid >> 1;         // 0..127
    const int ak   = (tid & 1) * 8;    // 0 or 8  (two float4s each)
    const int bk   = tid >> 4;         // 0..15
    const int bn   = (tid & 15) * 4;   // 0..60

    if (tid < EMB) sb2[tid] = b2[tid];
    __syncthreads();   // sb2 visible BEFORE the prologue STORE_TILE reads it

    float d[2][4][4];                  // [mtile][ntile][frag]
#pragma unroll
    for (int mt = 0; mt < 2; mt++)
#pragma unroll
        for (int nt = 0; nt < 4; nt++)
#pragma unroll
            for (int q = 0; q < 4; q++) d[mt][nt][q] = 0.f;

    const float* arowp = g_agg + (size_t)(row0 + arow) * LAT;
    const int  anode0  = (row0 + arow) * 82;
    const int  gc_b    = col0 + bn;

    // prefetch registers
    float4 pva[2]; float pdv[2]; float4 pvb;

    // ---- prefetch helper (expanded inline twice) ----
#define PREFETCH(K0)                                                        \
    {                                                                       \
        _Pragma("unroll")                                                   \
        for (int h = 0; h < 2; h++) {                                       \
            int c = (K0) + ak + 4 * h;                                      \
            if (c < LAT) {                                                  \
                pva[h] = *(const float4*)(arowp + c);                       \
                pdv[h] = __ldg(&g_dinv[anode0 + c / 20]);                   \
            } else {                                                        \
                pva[h] = make_float4(0.f, 0.f, 0.f, 0.f);                   \
                pdv[h] = 0.f;                                               \
            }                                                               \
        }                                                                   \
        pvb = make_float4(0.f, 0.f, 0.f, 0.f);                              \
        if (gc_b < HID && ((K0) + bk) < LAT)                                \
            pvb = *(const float4*)(Wf + (size_t)((K0) + bk) * HID + gc_b);  \
    }

#define STORE_TILE(BUF, K0)                                                 \
    {                                                                       \
        _Pragma("unroll")                                                   \
        for (int h = 0; h < 2; h++) {                                       \
            int c = (K0) + ak + 4 * h;                                      \
            int f0 = (c < LAT) ? (c % 20) : 0;                              \
            float dv = pdv[h];                                              \
            As[BUF][ak + 4*h + 0][arow] = cvt_tf32(fmaxf(fmaf(pva[h].x, dv, (c < LAT) ? sb2[f0 + 0] : 0.f), 0.f)); \
            As[BUF][ak + 4*h + 1][arow] = cvt_tf32(fmaxf(fmaf(pva[h].y, dv, (c < LAT) ? sb2[f0 + 1] : 0.f), 0.f)); \
            As[BUF][ak + 4*h + 2][arow] = cvt_tf32(fmaxf(fmaf(pva[h].z, dv, (c < LAT) ? sb2[f0 + 2] : 0.f), 0.f)); \
            As[BUF][ak + 4*h + 3][arow] = cvt_tf32(fmaxf(fmaf(pva[h].w, dv, (c < LAT) ? sb2[f0 + 3] : 0.f), 0.f)); \
        }                                                                   \
        Bs[BUF][bk][bn]     = cvt_tf32(pvb.x);                              \
        Bs[BUF][bk][bn + 1] = cvt_tf32(pvb.y);                              \
        Bs[BUF][bk][bn + 2] = cvt_tf32(pvb.z);                              \
        Bs[BUF][bk][bn + 3] = cvt_tf32(pvb.w);                              \
    }

    // prologue: tile 0 -> buffer 0
    PREFETCH(0);
    STORE_TILE(0, 0);
    __syncthreads();

    for (int i = 0; i < NITER; i++) {
        int buf = i & 1;
        int knext = (i + 1) * BK;
        if (i + 1 < NITER) PREFETCH(knext);

        // two k=8 sub-steps on current buffer
#pragma unroll
        for (int kk = 0; kk < BK; kk += 8) {
            unsigned a[2][4], b[4][2];
#pragma unroll
            for (int mt = 0; mt < 2; mt++) {
                int wr = warp_m * 32 + mt * 16 + g;
                a[mt][0] = As[buf][kk + tg][wr];
                a[mt][1] = As[buf][kk + tg][wr + 8];
                a[mt][2] = As[buf][kk + tg + 4][wr];
                a[mt][3] = As[buf][kk + tg + 4][wr + 8];
            }
#pragma unroll
            for (int nt = 0; nt < 4; nt++) {
                int wc = warp_n * 32 + nt * 8 + g;
                b[nt][0] = Bs[buf][kk + tg][wc];
                b[nt][1] = Bs[buf][kk + tg + 4][wc];
            }
#pragma unroll
            for (int mt = 0; mt < 2; mt++)
#pragma unroll
                for (int nt = 0; nt < 4; nt++)
                    mma_tf32(d[mt][nt][0], d[mt][nt][1], d[mt][nt][2], d[mt][nt][3],
                             a[mt][0], a[mt][1], a[mt][2], a[mt][3],
                             b[nt][0], b[nt][1]);
        }

        if (i + 1 < NITER) {
            STORE_TILE(buf ^ 1, knext);
            __syncthreads();
        }
    }
#undef PREFETCH
#undef STORE_TILE

    // epilogue: bias + relu -> g_fc1 (float2 stores; HID even, cols even)
#pragma unroll
    for (int mt = 0; mt < 2; mt++) {
        int r = row0 + warp_m * 32 + mt * 16 + g;
#pragma unroll
        for (int nt = 0; nt < 4; nt++) {
            int c = col0 + warp_n * 32 + nt * 8 + tg * 2;
            if (c < HID) {
                float b0 = bf[c], b1 = bf[c + 1];
                float2 lo = make_float2(fmaxf(d[mt][nt][0] + b0, 0.f),
                                        fmaxf(d[mt][nt][1] + b1, 0.f));
                float2 hi = make_float2(fmaxf(d[mt][nt][2] + b0, 0.f),
                                        fmaxf(d[mt][nt][3] + b1, 0.f));
                *(float2*)(g_fc1 + (size_t)r * HID + c)       = lo;
                *(float2*)(g_fc1 + (size_t)(r + 8) * HID + c) = hi;
            }
        }
    }
}

// out: [8192,300] @ [300,22] + out_b
__global__ __launch_bounds__(256) void k_out(const float* __restrict__ Wo,
                                             const float* __restrict__ bo,
                                             float* __restrict__ out) {
    __shared__ float sW[HID * NC];
    __shared__ float sb[NC];
    for (int t = threadIdx.x; t < HID * NC; t += 256) sW[t] = Wo[t];
    if (threadIdx.x < NC) sb[threadIdx.x] = bo[threadIdx.x];
    __syncthreads();
    int w = threadIdx.x >> 5, lane = threadIdx.x & 31;
    int rbase = blockIdx.x * 64 + w * 8;
#pragma unroll 1
    for (int r8 = 0; r8 < 8; r8++) {
        int r = rbase + r8;
        const float4* fr4 = (const float4*)(g_fc1 + (size_t)r * HID);
        if (lane < NC) {
            float accv = 0.f;
#pragma unroll 5
            for (int k4 = 0; k4 < HID / 4; k4++) {
                float4 v = fr4[k4];
                int k = 4 * k4;
                accv = fmaf(v.x, sW[(k + 0) * NC + lane], accv);
                accv = fmaf(v.y, sW[(k + 1) * NC + lane], accv);
                accv = fmaf(v.z, sW[(k + 2) * NC + lane], accv);
                accv = fmaf(v.w, sW[(k + 3) * NC + lane], accv);
            }
            out[(size_t)r * NC + lane] = accv + sb[lane];
        }
    }
}

// ---------------- launch --------------------------------------------------
extern "C" void kernel_launch(void* const* d_in, const int* in_sizes, int n_in,
                              void* d_out, int out_size) {
    const float* x    = (const float*)d_in[0];
    const void*  ei   = d_in[1];
    const float* W1   = (const float*)d_in[3];
    const float* b1   = (const float*)d_in[4];
    const float* W2   = (const float*)d_in[5];
    const float* b2   = (const float*)d_in[6];
    const float* fc1W = (const float*)d_in[7];
    const float* fc1b = (const float*)d_in[8];
    const float* outW = (const float*)d_in[9];
    const float* outb = (const float*)d_in[10];
    float* out = (float*)d_out;

    int N = in_sizes[0] / SEQL;
    int E = in_sizes[1] / 2;
    int rows = out_size / NC;                // 8192
    int nb = (N + 255) / 256;
    int eb = (E + 255) / 256;

    k_init<<<nb, 256>>>((const int*)ei, N);     // 1
    k_edges_prep<<<eb, 256>>>(ei, E);           // 2
    k_layer1<<<nb, 256>>>(x, W1, N);            // 3
    k_scatter<<<eb, 256>>>(E);                  // 4  <-- ncu slot (sentinel)
    k_layer2<<<nb, 256>>>(b1, W2, N);           // 5
    k_scatter<<<eb, 256>>>(E);                  // 6
    dim3 gfc(rows / BM, (HID + BN - 1) / BN);
    k_fc1<<<gfc, 256>>>(fc1W, fc1b, b2);        // 7 (fused final)
    k_out<<<rows / 64, 256>>>(outW, outb, out); // 8
}

// round 17
// speedup vs baseline: 1.0120x; 1.0120x over previous
#include <cuda_runtime.h>
#include <cuda_fp16.h>

#define SEQL 20
#define EMB  20
#define NMAX 671744
#define EMAX 4000000
#define NBATCH 8192
#define HID  300
#define NC   22
#define LAT  1640   // 82*20

// ---------------- scratch (static device globals; no runtime alloc) -------
__device__ int   g_deg[NMAX];
__device__ float g_dinv[NMAX];
__device__ __align__(16) uint4 g_hsh[(size_t)NMAX * 3];   // fp16 messages, 48B/row (40B valid)
__device__ float g_agg[(size_t)NMAX * EMB];   // fp32 aggregation buffer
__device__ int   g_src[EMAX];
__device__ int   g_dst[EMAX];
__device__ float g_fc1[(size_t)NBATCH * HID];
__device__ int   g_is64;

// ---------------- helpers -------------------------------------------------
__device__ __forceinline__ void red_add_v4(float* p, float4 v) {
    asm volatile("red.global.add.v4.f32 [%0], {%1,%2,%3,%4};"
                 :: "l"(p), "f"(v.x), "f"(v.y), "f"(v.z), "f"(v.w) : "memory");
}
__device__ __forceinline__ unsigned cvt_tf32(float f) {
    unsigned u;
    asm("cvt.rna.tf32.f32 %0, %1;" : "=r"(u) : "f"(f));
    return u;
}
__device__ __forceinline__ void mma_tf32(float& d0, float& d1, float& d2, float& d3,
                                         unsigned a0, unsigned a1, unsigned a2, unsigned a3,
                                         unsigned b0, unsigned b1) {
    asm("mma.sync.aligned.m16n8k8.row.col.f32.tf32.tf32.f32 "
        "{%0,%1,%2,%3}, {%4,%5,%6,%7}, {%8,%9}, {%0,%1,%2,%3};"
        : "+f"(d0), "+f"(d1), "+f"(d2), "+f"(d3)
        : "r"(a0), "r"(a1), "r"(a2), "r"(a3), "r"(b0), "r"(b1));
}
__device__ __forceinline__ unsigned smem_u32(const void* p) {
    unsigned a;
    asm("{ .reg .u64 t; cvta.to.shared.u64 t, %1; cvt.u32.u64 %0, t; }"
        : "=r"(a) : "l"(p));
    return a;
}
__device__ __forceinline__ void ldsm_x4(unsigned& r0, unsigned& r1,
                                        unsigned& r2, unsigned& r3, unsigned addr) {
    asm volatile("ldmatrix.sync.aligned.m8n8.x4.shared.b16 {%0,%1,%2,%3}, [%4];"
                 : "=r"(r0), "=r"(r1), "=r"(r2), "=r"(r3) : "r"(addr));
}
// write one node row: o[0..19]*dinv -> fp16x2 packed 48B (+agg fp32 seed)
__device__ __forceinline__ void store_row(int i, const float* o, float dinv) {
    __half2 hh[12];
#pragma unroll
    for (int j = 0; j < 10; j++)
        hh[j] = __floats2half2_rn(o[2*j] * dinv, o[2*j+1] * dinv);
    hh[10] = hh[11] = __float2half2_rn(0.f);
    uint4* hp = &g_hsh[(size_t)i * 3];
    const uint4* src = (const uint4*)hh;
    hp[0] = src[0]; hp[1] = src[1]; hp[2] = src[2];
    float4* ap = (float4*)(g_agg + (size_t)i * EMB);
#pragma unroll
    for (int q = 0; q < EMB / 4; q++)
        ap[q] = make_float4(o[4*q]*dinv, o[4*q+1]*dinv, o[4*q+2]*dinv, o[4*q+3]*dinv);
}

// ---- launch 1: dtype detect + deg := 1 (self loop) -----------------------
__global__ void k_init(const int* __restrict__ ei32, int n) {
    int i = blockIdx.x * blockDim.x + threadIdx.x;
    if (i < n) g_deg[i] = 1;           // self loop
    if (blockIdx.x == 0 && threadIdx.x == 0) {
        int all0 = 1;
        for (int q = 1; q < 257; q += 2)
            if (ei32[q] != 0) { all0 = 0; break; }
        g_is64 = all0;   // int64 little-endian: high words of small values are 0
    }
}

// ---- launch 2: stage edges to int32 + degree count -----------------------
__global__ void k_edges_prep(const void* __restrict__ eiv, int E) {
    int e = blockIdx.x * blockDim.x + threadIdx.x;
    if (e >= E) return;
    int s, d;
    if (g_is64) {
        const long long* p = (const long long*)eiv;
        s = (int)p[e];
        d = (int)p[(size_t)E + e];
    } else {
        const int* p = (const int*)eiv;
        s = p[e];
        d = p[E + e];
    }
    g_src[e] = s;
    g_dst[e] = d;
    atomicAdd(&g_deg[d], 1);
}

// ---- launch 3: msg(fp16) = (x @ W1)*dinv ; agg(fp32) = same (self seed) --
__global__ __launch_bounds__(256) void k_layer1(const float* __restrict__ x,
                                                const float* __restrict__ W,
                                                int n) {
    __shared__ __align__(16) float sW[SEQL * EMB];
    for (int t = threadIdx.x; t < SEQL * EMB; t += 256) sW[t] = W[t];
    __syncthreads();
    int i = blockIdx.x * 256 + threadIdx.x;
    if (i >= n) return;
    float dinv = rsqrtf((float)g_deg[i]);
    g_dinv[i] = dinv;
    float xi[SEQL];
    const float4* xp = (const float4*)(x + (size_t)i * SEQL);
#pragma unroll
    for (int q = 0; q < SEQL / 4; q++) {
        float4 v = __ldg(xp + q);
        xi[4*q] = v.x; xi[4*q+1] = v.y; xi[4*q+2] = v.z; xi[4*q+3] = v.w;
    }
    float o[EMB];
#pragma unroll
    for (int j = 0; j < EMB; j++) o[j] = 0.f;
#pragma unroll
    for (int k = 0; k < SEQL; k++) {
        float xk = xi[k];
#pragma unroll
        for (int q = 0; q < EMB / 4; q++) {
            float4 w = *(const float4*)&sW[k * EMB + 4 * q];
            o[4*q]   = fmaf(xk, w.x, o[4*q]);
            o[4*q+1] = fmaf(xk, w.y, o[4*q+1]);
            o[4*q+2] = fmaf(xk, w.z, o[4*q+2]);
            o[4*q+3] = fmaf(xk, w.w, o[4*q+3]);
        }
    }
    store_row(i, o, dinv);
}

// ---- launch 4 (ncu slot): agg[dst] += msg[src]  (48B fp16 read, fp32 RED)
__global__ __launch_bounds__(256) void k_scatter(int E) {
    int e = blockIdx.x * blockDim.x + threadIdx.x;
    if (e >= E) return;
    int s = g_src[e], d = g_dst[e];
    const uint4* hp = &g_hsh[(size_t)s * 3];
    uint4 u0 = __ldg(hp), u1 = __ldg(hp + 1), u2 = __ldg(hp + 2);
    __half2 hh[12];
    uint4* hv = (uint4*)hh;
    hv[0] = u0; hv[1] = u1; hv[2] = u2;
    float f[EMB];
#pragma unroll
    for (int j = 0; j < 10; j++) {
        float2 t = __half22float2(hh[j]);
        f[2*j] = t.x; f[2*j+1] = t.y;
    }
    float* ap = g_agg + (size_t)d * EMB;
#pragma unroll
    for (int q = 0; q < EMB / 4; q++)
        red_add_v4(ap + 4 * q, make_float4(f[4*q], f[4*q+1], f[4*q+2], f[4*q+3]));
}

// ---- t = relu(agg*dinv + b1);  o = (t @ W2)*dinv -> msg fp16 + agg seed --
__global__ __launch_bounds__(256) void k_layer2(const float* __restrict__ b1,
                                                const float* __restrict__ W,
                                                int n) {
    __shared__ __align__(16) float sW[EMB * EMB];
    __shared__ float sb[EMB];
    for (int t = threadIdx.x; t < EMB * EMB; t += 256) sW[t] = W[t];
    if (threadIdx.x < EMB) sb[threadIdx.x] = b1[threadIdx.x];
    __syncthreads();
    int i = blockIdx.x * 256 + threadIdx.x;
    if (i >= n) return;
    float dinv = g_dinv[i];
    float ti[EMB];
    const float4* ap_in = (const float4*)(g_agg + (size_t)i * EMB);
#pragma unroll
    for (int q = 0; q < EMB / 4; q++) {
        float4 v = ap_in[q];
        ti[4*q]   = fmaxf(fmaf(v.x, dinv, sb[4*q]),   0.f);
        ti[4*q+1] = fmaxf(fmaf(v.y, dinv, sb[4*q+1]), 0.f);
        ti[4*q+2] = fmaxf(fmaf(v.z, dinv, sb[4*q+2]), 0.f);
        ti[4*q+3] = fmaxf(fmaf(v.w, dinv, sb[4*q+3]), 0.f);
    }
    float o[EMB];
#pragma unroll
    for (int j = 0; j < EMB; j++) o[j] = 0.f;
#pragma unroll
    for (int k = 0; k < EMB; k++) {
        float tk = ti[k];
#pragma unroll
        for (int q = 0; q < EMB / 4; q++) {
            float4 w = *(const float4*)&sW[k * EMB + 4 * q];
            o[4*q]   = fmaf(tk, w.x, o[4*q]);
            o[4*q+1] = fmaf(tk, w.y, o[4*q+1]);
            o[4*q+2] = fmaf(tk, w.z, o[4*q+2]);
            o[4*q+3] = fmaf(tk, w.w, o[4*q+3]);
        }
    }
    store_row(i, o, dinv);
}

// fc1 (tf32 tensor cores, fused final, double-buffered, ldmatrix frags):
// A[r][c] = relu(agg[r*1640+c]*dinv + b2) computed in the A-tile load.
// BM=128 BN=64 BK=16; 8 warps (4x2), warp tile 32x32; mma.m16n8k8.
// A stored [m][k] stride 20; B stored transposed [n][k] stride 20.
// Stride-20 words => 8 consecutive rows hit banks {0,20,8,28,16,4,24,12}: no conflicts.
#define BM 128
#define BN 64
#define BK 16
#define AST 20                       // padded k-stride (words)
#define NITER ((LAT + BK - 1) / BK)  // 103
__global__ __launch_bounds__(256) void k_fc1(const float* __restrict__ Wf,
                                             const float* __restrict__ bf,
                                             const float* __restrict__ b2) {
    __shared__ __align__(16) unsigned As2[2][BM][AST];  // [buf][m][k]
    __shared__ __align__(16) unsigned BsT[2][BN][AST];  // [buf][n][k]
    __shared__ float sb2[EMB];
    const int tid  = threadIdx.x;
    const int lane = tid & 31;
    const int wid  = tid >> 5;         // 0..7
    const int warp_m = wid & 3;        // 0..3  (32 rows each)
    const int warp_n = wid >> 2;       // 0..1  (32 cols each)
    const int row0 = blockIdx.x * BM;
    const int col0 = blockIdx.y * BN;
    const int g  = lane >> 2;          // 0..7
    const int tg = lane & 3;           // 0..3

    const int arow = tid >> 1;         // 0..127
    const int ak   = (tid & 1) * 8;    // 0 or 8  (two float4s each)
    const int bk   = tid >> 4;         // 0..15
    const int bn   = (tid & 15) * 4;   // 0..60

    if (tid < EMB) sb2[tid] = b2[tid];
    __syncthreads();   // sb2 visible before prologue store

    float d[2][4][4];                  // [mtile][ntile][frag]
#pragma unroll
    for (int mt = 0; mt < 2; mt++)
#pragma unroll
        for (int nt = 0; nt < 4; nt++)
#pragma unroll
            for (int q = 0; q < 4; q++) d[mt][nt][q] = 0.f;

    const float* arowp = g_agg + (size_t)(row0 + arow) * LAT;
    const int  anode0  = (row0 + arow) * 82;
    const int  gc_b    = col0 + bn;

    // ldmatrix lane address offsets (bytes), invariant part
    const int qm = lane >> 3;          // matrix index 0..3
    const int lr = lane & 7;           // row within matrix
    // A: matrices = {m+0/k+0, m+8/k+0, m+0/k+4, m+8/k+4}
    const unsigned a_off = (unsigned)(((warp_m * 32 + lr + (qm & 1) * 8) * AST
                                       + (qm >> 1) * 4) * 4);
    // B: matrices = {n-tile even/k0, even/k4, odd/k0, odd/k4}
    const unsigned b_off = (unsigned)(((warp_n * 32 + (qm >> 1) * 8 + lr) * AST
                                       + (qm & 1) * 4) * 4);
    const unsigned As_base = smem_u32(&As2[0][0][0]);
    const unsigned Bs_base = smem_u32(&BsT[0][0][0]);
    const unsigned ASZ = BM * AST * 4;   // bytes per A buffer
    const unsigned BSZ = BN * AST * 4;   // bytes per B buffer

    // prefetch registers
    float4 pva[2]; float pdv[2]; float4 pvb;

#define PREFETCH(K0)                                                        \
    {                                                                       \
        _Pragma("unroll")                                                   \
        for (int h = 0; h < 2; h++) {                                       \
            int c = (K0) + ak + 4 * h;                                      \
            if (c < LAT) {                                                  \
                pva[h] = *(const float4*)(arowp + c);                       \
                pdv[h] = __ldg(&g_dinv[anode0 + c / 20]);                   \
            } else {                                                        \
                pva[h] = make_float4(0.f, 0.f, 0.f, 0.f);                   \
                pdv[h] = 0.f;                                               \
            }                                                               \
        }                                                                   \
        pvb = make_float4(0.f, 0.f, 0.f, 0.f);                              \
        if (gc_b < HID && ((K0) + bk) < LAT)                                \
            pvb = *(const float4*)(Wf + (size_t)((K0) + bk) * HID + gc_b);  \
    }

#define STORE_TILE(BUF, K0)                                                 \
    {                                                                       \
        _Pragma("unroll")                                                   \
        for (int h = 0; h < 2; h++) {                                       \
            int c = (K0) + ak + 4 * h;                                      \
            int f0 = (c < LAT) ? (c % 20) : 0;                              \
            float dv = pdv[h];                                              \
            uint4 w;                                                        \
            w.x = cvt_tf32(fmaxf(fmaf(pva[h].x, dv, (c < LAT) ? sb2[f0 + 0] : 0.f), 0.f)); \
            w.y = cvt_tf32(fmaxf(fmaf(pva[h].y, dv, (c < LAT) ? sb2[f0 + 1] : 0.f), 0.f)); \
            w.z = cvt_tf32(fmaxf(fmaf(pva[h].z, dv, (c < LAT) ? sb2[f0 + 2] : 0.f), 0.f)); \
            w.w = cvt_tf32(fmaxf(fmaf(pva[h].w, dv, (c < LAT) ? sb2[f0 + 3] : 0.f), 0.f)); \
            *(uint4*)&As2[BUF][arow][ak + 4 * h] = w;                       \
        }                                                                   \
        BsT[BUF][bn + 0][bk] = cvt_tf32(pvb.x);                             \
        BsT[BUF][bn + 1][bk] = cvt_tf32(pvb.y);                             \
        BsT[BUF][bn + 2][bk] = cvt_tf32(pvb.z);                             \
        BsT[BUF][bn + 3][bk] = cvt_tf32(pvb.w);                             \
    }

    // prologue: tile 0 -> buffer 0
    PREFETCH(0);
    STORE_TILE(0, 0);
    __syncthreads();

    for (int i = 0; i < NITER; i++) {
        int buf = i & 1;
        int knext = (i + 1) * BK;
        if (i + 1 < NITER) PREFETCH(knext);

        unsigned abase = As_base + (unsigned)buf * ASZ + a_off;
        unsigned bbase = Bs_base + (unsigned)buf * BSZ + b_off;

        // two k=8 sub-steps on current buffer
#pragma unroll
        for (int kk = 0; kk < BK; kk += 8) {
            unsigned a[2][4], b[4][2];
            ldsm_x4(a[0][0], a[0][1], a[0][2], a[0][3], abase + (unsigned)(kk * 4));
            ldsm_x4(a[1][0], a[1][1], a[1][2], a[1][3],
                    abase + (unsigned)(16 * AST * 4 + kk * 4));
            ldsm_x4(b[0][0], b[0][1], b[1][0], b[1][1], bbase + (unsigned)(kk * 4));
            ldsm_x4(b[2][0], b[2][1], b[3][0], b[3][1],
                    bbase + (unsigned)(16 * AST * 4 + kk * 4));
#pragma unroll
            for (int mt = 0; mt < 2; mt++)
#pragma unroll
                for (int nt = 0; nt < 4; nt++)
                    mma_tf32(d[mt][nt][0], d[mt][nt][1], d[mt][nt][2], d[mt][nt][3],
                             a[mt][0], a[mt][1], a[mt][2], a[mt][3],
                             b[nt][0], b[nt][1]);
        }

        if (i + 1 < NITER) {
            STORE_TILE(buf ^ 1, knext);
            __syncthreads();
        }
    }
#undef PREFETCH
#undef STORE_TILE

    // epilogue: bias + relu -> g_fc1 (float2 stores; HID even, cols even)
#pragma unroll
    for (int mt = 0; mt < 2; mt++) {
        int r = row0 + warp_m * 32 + mt * 16 + g;
#pragma unroll
        for (int nt = 0; nt < 4; nt++) {
            int c = col0 + warp_n * 32 + nt * 8 + tg * 2;
            if (c < HID) {
                float b0 = bf[c], b1 = bf[c + 1];
                float2 lo = make_float2(fmaxf(d[mt][nt][0] + b0, 0.f),
                                        fmaxf(d[mt][nt][1] + b1, 0.f));
                float2 hi = make_float2(fmaxf(d[mt][nt][2] + b0, 0.f),
                                        fmaxf(d[mt][nt][3] + b1, 0.f));
                *(float2*)(g_fc1 + (size_t)r * HID + c)       = lo;
                *(float2*)(g_fc1 + (size_t)(r + 8) * HID + c) = hi;
            }
        }
    }
}

// out: [8192,300] @ [300,22] + out_b
__global__ __launch_bounds__(256) void k_out(const float* __restrict__ Wo,
                                             const float* __restrict__ bo,
                                             float* __restrict__ out) {
    __shared__ float sW[HID * NC];
    __shared__ float sb[NC];
    for (int t = threadIdx.x; t < HID * NC; t += 256) sW[t] = Wo[t];
    if (threadIdx.x < NC) sb[threadIdx.x] = bo[threadIdx.x];
    __syncthreads();
    int w = threadIdx.x >> 5, lane = threadIdx.x & 31;
    int rbase = blockIdx.x * 64 + w * 8;
#pragma unroll 1
    for (int r8 = 0; r8 < 8; r8++) {
        int r = rbase + r8;
        const float4* fr4 = (const float4*)(g_fc1 + (size_t)r * HID);
        if (lane < NC) {
            float accv = 0.f;
#pragma unroll 5
            for (int k4 = 0; k4 < HID / 4; k4++) {
                float4 v = fr4[k4];
                int k = 4 * k4;
                accv = fmaf(v.x, sW[(k + 0) * NC + lane], accv);
                accv = fmaf(v.y, sW[(k + 1) * NC + lane], accv);
                accv = fmaf(v.z, sW[(k + 2) * NC + lane], accv);
                accv = fmaf(v.w, sW[(k + 3) * NC + lane], accv);
            }
            out[(size_t)r * NC + lane] = accv + sb[lane];
        }
    }
}

// ---------------- launch --------------------------------------------------
extern "C" void kernel_launch(void* const* d_in, const int* in_sizes, int n_in,
                              void* d_out, int out_size) {
    const float* x    = (const float*)d_in[0];
    const void*  ei   = d_in[1];
    const float* W1   = (const float*)d_in[3];
    const float* b1   = (const float*)d_in[4];
    const float* W2   = (const float*)d_in[5];
    const float* b2   = (const float*)d_in[6];
    const float* fc1W = (const float*)d_in[7];
    const float* fc1b = (const float*)d_in[8];
    const float* outW = (const float*)d_in[9];
    const float* outb = (const float*)d_in[10];
    float* out = (float*)d_out;

    int N = in_sizes[0] / SEQL;
    int E = in_sizes[1] / 2;
    int rows = out_size / NC;                // 8192
    int nb = (N + 255) / 256;
    int eb = (E + 255) / 256;

    k_init<<<nb, 256>>>((const int*)ei, N);     // 1
    k_edges_prep<<<eb, 256>>>(ei, E);           // 2
    k_layer1<<<nb, 256>>>(x, W1, N);            // 3
    k_scatter<<<eb, 256>>>(E);                  // 4  <-- ncu slot (sentinel)
    k_layer2<<<nb, 256>>>(b1, W2, N);           // 5
    k_scatter<<<eb, 256>>>(E);                  // 6
    dim3 gfc(rows / BM, (HID + BN - 1) / BN);
    k_fc1<<<gfc, 256>>>(fc1W, fc1b, b2);        // 7 (fused final)
    k_out<<<rows / 64, 256>>>(outW, outb, out); // 8
}